// round 16
// baseline (speedup 1.0000x reference)
#include <cuda_runtime.h>
#include <cuda_fp16.h>
#include <stdint.h>
#include <math.h>

#define BATCH 8
#define SEQ   2048
#define DIM   1024
#define MTOT  (BATCH * SEQ)

// ---------------------------------------------------------------------------
// Static device scratch (allocation-free contract). V is never materialized
// (QKV z==2 epilogue writes Vt). S is never materialized in fp32: the E GEMM
// epilogue applies exp2 and writes unnormalized E (fp16); normalization is
// folded into the PV epilogue via per-row 1/sum.
// ---------------------------------------------------------------------------
__device__ __align__(256) __half g_xH[(size_t)MTOT * DIM];
__device__ __align__(256) __half g_WtH[4][(size_t)DIM * DIM];
__device__ __align__(256) __half g_Q[(size_t)MTOT * DIM];
__device__ __align__(256) __half g_K[(size_t)MTOT * DIM];
__device__ __align__(256) __half g_Vt[(size_t)MTOT * DIM];
__device__ __align__(256) __half g_O[(size_t)MTOT * DIM];
__device__ __align__(256) __half g_E[(size_t)BATCH * SEQ * SEQ];
__device__ __align__(256) float  g_Rinv[(size_t)MTOT];

// ---------------------------------------------------------------------------
// Helpers (arch-agnostic PTX only: cp.async / ldmatrix / mma.sync)
// ---------------------------------------------------------------------------
__device__ __forceinline__ uint32_t smem_to_u32(const void* smem_ptr) {
    uint32_t addr;
    asm("{ .reg .u64 tmp; cvta.to.shared.u64 tmp, %1; cvt.u32.u64 %0, tmp; }"
        : "=r"(addr) : "l"(smem_ptr));
    return addr;
}
#define SMEM_SWIZZLE_128B(byte_offset) \
    ((byte_offset) ^ (((byte_offset) >> 3) & 0x70))
#define CP_ASYNC_16(dst_u32, src_ptr) \
    asm volatile("cp.async.cg.shared.global [%0], [%1], 16;" \
                 :: "r"(dst_u32), "l"(src_ptr) : "memory")
#define CP_COMMIT() asm volatile("cp.async.commit_group;" ::: "memory")
#define CP_WAIT(n)  asm volatile("cp.async.wait_group %0;" :: "n"(n) : "memory")

#define LDMATRIX_X4(r0, r1, r2, r3, addr) \
    asm volatile("ldmatrix.sync.aligned.m8n8.x4.shared.b16 {%0,%1,%2,%3}, [%4];" \
                 : "=r"(r0), "=r"(r1), "=r"(r2), "=r"(r3) : "r"(addr))

#define MMA_F16(c, a, b0, b1) \
    asm volatile("mma.sync.aligned.m16n8k16.row.col.f32.f16.f16.f32 " \
                 "{%0,%1,%2,%3}, {%4,%5,%6,%7}, {%8,%9}, {%0,%1,%2,%3};" \
                 : "+f"((c)[0]), "+f"((c)[1]), "+f"((c)[2]), "+f"((c)[3]) \
                 : "r"((a)[0]), "r"((a)[1]), "r"((a)[2]), "r"((a)[3]), \
                   "r"(b0), "r"(b1))

// ---------------------------------------------------------------------------
// GEMM: D[M,N] = A@B^T, single-pass fp16 inputs, fp32 accumulate.
// R8-proven config: tile 128x128, BK=64 (128B rows, SW128), 2-stage cp.async
// double buffer, 8 warps (4m x 2n), warp tile 32x64 m16n8k16, 2 CTAs/SM.
// EPI: 0 = fp32 out, 1 = fp32 + bias, 2 = fp16 out,
//      3 = fp16 exp2(acc) out (unnormalized attention weights E),
//      4 = fp16 acc * rinv[row] out (normalized PV; bias ptr = rinv floats,
//          indexed blockIdx.z * SEQ + row).
// MULTI_B: blockIdx.z selects weight set; z==0 -> Ch (Q), z==1 -> C1 (K),
//          z==2 -> TRANSPOSED fp16 write into C2 as per-batch Vt[DIM,SEQ].
// rowOff: global row offset of this launch's tile grid.
// ---------------------------------------------------------------------------
#define TILE_BYTES 16384            // 128 rows x 128B
#define STAGE_BYTES (2 * TILE_BYTES)
#define SM_TOTAL (2 * STAGE_BYTES)  // 65536

template <int EPI, bool MULTI_B>
__global__ void __launch_bounds__(256, 2)
gemmh_kernel(const __half* __restrict__ A, const __half* __restrict__ B,
             float* __restrict__ Cf, __half* __restrict__ Ch,
             __half* __restrict__ C1, __half* __restrict__ C2,
             const float* __restrict__ bias,
             int K, int ldC, size_t sA, size_t sB, size_t sC, int rowOff)
{
    extern __shared__ char smem[];
    const uint32_t smem_u = smem_to_u32(smem);
    const int tid = threadIdx.x;
    const int lane = tid & 31;
    const int wid = tid >> 5;
    const int warp_m = wid & 3;
    const int warp_n = wid >> 2;
    const int rowBase = rowOff + blockIdx.y * 128;
    const int colBase = blockIdx.x * 128;
    const size_t zA = MULTI_B ? 0 : (size_t)blockIdx.z * sA;
    const size_t zB = (size_t)blockIdx.z * sB;
    const size_t zC = MULTI_B ? 0 : (size_t)blockIdx.z * sC;
    __half* ChSel = Ch;
    if (MULTI_B) ChSel = (blockIdx.z == 0) ? Ch : ((blockIdx.z == 1) ? C1 : C2);

    const int ldr_row0 = tid >> 3;
    const int ldr_ch   = tid & 7;

    float acc[2][8][4];
#pragma unroll
    for (int i = 0; i < 2; i++)
#pragma unroll
        for (int j = 0; j < 8; j++)
#pragma unroll
            for (int e = 0; e < 4; e++) acc[i][j][e] = 0.0f;

    const int nIter = K >> 6;

    auto issue_load = [&](int i, int stage) {
        const int kk = i << 6;
        const __half* As = A + zA;
        const __half* Bs = B + zB;
        const uint32_t aBase = smem_u + stage * STAGE_BYTES;
        const uint32_t bBase = aBase + TILE_BYTES;
#pragma unroll
        for (int p = 0; p < 4; p++) {
            const int row = ldr_row0 + p * 32;
            const uint32_t soff = SMEM_SWIZZLE_128B((uint32_t)row * 128 + ldr_ch * 16);
            CP_ASYNC_16(aBase + soff,
                        As + (size_t)(rowBase + row) * K + kk + ldr_ch * 8);
            CP_ASYNC_16(bBase + soff,
                        Bs + (size_t)(colBase + row) * K + kk + ldr_ch * 8);
        }
        CP_COMMIT();
    };

    issue_load(0, 0);

    for (int i = 0; i < nIter; i++) {
        const int stage = i & 1;
        if (i + 1 < nIter) {
            issue_load(i + 1, (i + 1) & 1);
            CP_WAIT(1);
        } else {
            CP_WAIT(0);
        }
        __syncthreads();

        const uint32_t aBase = smem_u + stage * STAGE_BYTES;
        const uint32_t bBase = aBase + TILE_BYTES;
#pragma unroll
        for (int ks = 0; ks < 4; ks++) {
            const uint32_t k2 = ks * 32;
            uint32_t a[2][4];
            uint32_t b[4][4];
#pragma unroll
            for (int fm = 0; fm < 2; fm++) {
                const uint32_t row = warp_m * 32 + fm * 16 + (lane & 15);
                const uint32_t addr = aBase +
                    SMEM_SWIZZLE_128B(row * 128 + k2 + ((lane >> 4) << 4));
                LDMATRIX_X4(a[fm][0], a[fm][1], a[fm][2], a[fm][3], addr);
            }
#pragma unroll
            for (int fn2 = 0; fn2 < 4; fn2++) {
                const uint32_t n = warp_n * 64 + fn2 * 16 + (lane & 7) + ((lane >> 4) << 3);
                const uint32_t addr = bBase +
                    SMEM_SWIZZLE_128B(n * 128 + k2 + (((lane >> 3) & 1) << 4));
                LDMATRIX_X4(b[fn2][0], b[fn2][1], b[fn2][2], b[fn2][3], addr);
            }
#pragma unroll
            for (int fn2 = 0; fn2 < 4; fn2++) {
                MMA_F16(acc[0][fn2 * 2 + 0], a[0], b[fn2][0], b[fn2][1]);
                MMA_F16(acc[0][fn2 * 2 + 1], a[0], b[fn2][2], b[fn2][3]);
                MMA_F16(acc[1][fn2 * 2 + 0], a[1], b[fn2][0], b[fn2][1]);
                MMA_F16(acc[1][fn2 * 2 + 1], a[1], b[fn2][2], b[fn2][3]);
            }
        }
        __syncthreads();
    }

    // Epilogue
    const int gid = lane >> 2;
    const int tig = lane & 3;

    if (EPI == 2 && MULTI_B && blockIdx.z == 2) {
        // ---- transposed V output: stage tile in smem, write Vt[d, t] ----
        __half* tsm = reinterpret_cast<__half*>(smem);   // [128][130] fp16
#pragma unroll
        for (int fm = 0; fm < 2; fm++) {
#pragma unroll
            for (int fn = 0; fn < 8; fn++) {
                const int r = warp_m * 32 + fm * 16 + gid;     // tile-local t
                const int c = warp_n * 64 + fn * 8 + tig * 2;  // tile-local d
                const float* ac = acc[fm][fn];
                __half2 h0 = __floats2half2_rn(ac[0], ac[1]);
                __half2 h1 = __floats2half2_rn(ac[2], ac[3]);
                *(__half2*)(&tsm[(size_t)r * 130 + c])       = h0;
                *(__half2*)(&tsm[(size_t)(r + 8) * 130 + c]) = h1;
            }
        }
        __syncthreads();
        const int gRow0 = rowBase;                    // 128-aligned, within one batch
        const size_t bidx = (size_t)gRow0 / SEQ;
        const int tl0 = gRow0 % SEQ;
        __half* dstBase = C2 + bidx * (size_t)DIM * SEQ + tl0;
#pragma unroll 1
        for (int ccb = 0; ccb < 16; ccb++) {
            const int cc = wid * 16 + ccb;            // tile-local d
            __half* drow = dstBase + (size_t)(colBase + cc) * SEQ;
#pragma unroll
            for (int j = 0; j < 4; j++) {
                const int t = lane + 32 * j;
                drow[t] = tsm[(size_t)t * 130 + cc];
            }
        }
        return;
    }

#pragma unroll
    for (int fm = 0; fm < 2; fm++) {
#pragma unroll
        for (int fn = 0; fn < 8; fn++) {
            const int r0 = rowBase + warp_m * 32 + fm * 16 + gid;
            const int c  = colBase + warp_n * 64 + fn * 8 + tig * 2;
            const float* ac = acc[fm][fn];
            if (EPI == 2) {
                __half2 h0 = __floats2half2_rn(ac[0], ac[1]);
                __half2 h1 = __floats2half2_rn(ac[2], ac[3]);
                *(uint32_t*)(ChSel + zC + (size_t)r0 * ldC + c)       = *(uint32_t*)&h0;
                *(uint32_t*)(ChSel + zC + (size_t)(r0 + 8) * ldC + c) = *(uint32_t*)&h1;
            } else if (EPI == 3) {
                __half2 h0 = __floats2half2_rn(exp2f(ac[0]), exp2f(ac[1]));
                __half2 h1 = __floats2half2_rn(exp2f(ac[2]), exp2f(ac[3]));
                *(uint32_t*)(ChSel + zC + (size_t)r0 * ldC + c)       = *(uint32_t*)&h0;
                *(uint32_t*)(ChSel + zC + (size_t)(r0 + 8) * ldC + c) = *(uint32_t*)&h1;
            } else if (EPI == 4) {
                const float rs0 = bias[(size_t)blockIdx.z * SEQ + r0];
                const float rs1 = bias[(size_t)blockIdx.z * SEQ + r0 + 8];
                __half2 h0 = __floats2half2_rn(ac[0] * rs0, ac[1] * rs0);
                __half2 h1 = __floats2half2_rn(ac[2] * rs1, ac[3] * rs1);
                *(uint32_t*)(ChSel + zC + (size_t)r0 * ldC + c)       = *(uint32_t*)&h0;
                *(uint32_t*)(ChSel + zC + (size_t)(r0 + 8) * ldC + c) = *(uint32_t*)&h1;
            } else {
                float2 v0 = make_float2(ac[0], ac[1]);
                float2 v1 = make_float2(ac[2], ac[3]);
                if (EPI == 1) {
                    const float b0 = bias[c], b1 = bias[c + 1];
                    v0.x += b0; v0.y += b1;
                    v1.x += b0; v1.y += b1;
                }
                *(float2*)(Cf + zC + (size_t)r0 * ldC + c)       = v0;
                *(float2*)(Cf + zC + (size_t)(r0 + 8) * ldC + c) = v1;
            }
        }
    }
}

// ---------------------------------------------------------------------------
// fp32 -> fp16 convert (elementwise)
// ---------------------------------------------------------------------------
__global__ void __launch_bounds__(256)
convert_fp16_kernel(const float* __restrict__ x, __half* __restrict__ h)
{
    size_t i = ((size_t)blockIdx.x * 256 + threadIdx.x) * 4;
    float4 v = *(const float4*)(x + i);
    __half2 a = __floats2half2_rn(v.x, v.y);
    __half2 b = __floats2half2_rn(v.z, v.w);
    *(uint2*)(h + i) = make_uint2(*(uint32_t*)&a, *(uint32_t*)&b);
}

// ---------------------------------------------------------------------------
// Transpose + convert ALL FOUR weight matrices in one launch.
// Wq (z==0) pre-scaled by scale*log2e -> E = exp2(logit) directly.
// ---------------------------------------------------------------------------
__global__ void __launch_bounds__(256)
transW_all_kernel(const float* __restrict__ W0, const float* __restrict__ W1,
                  const float* __restrict__ W2, const float* __restrict__ W3,
                  __half* __restrict__ thB, float qscale)
{
    const float* W = (blockIdx.z == 0) ? W0 :
                     (blockIdx.z == 1) ? W1 :
                     (blockIdx.z == 2) ? W2 : W3;
    const float sc = (blockIdx.z == 0) ? qscale : 1.0f;
    __half* th = thB + (size_t)blockIdx.z * DIM * DIM;
    __shared__ float t[32][33];
    const int tx = threadIdx.x, ty = threadIdx.y;
    const int x = blockIdx.x * 32 + tx;
    const int y0 = blockIdx.y * 32;
#pragma unroll
    for (int p = 0; p < 4; p++)
        t[ty + 8 * p][tx] = W[(size_t)(y0 + ty + 8 * p) * DIM + x];
    __syncthreads();
    const int ox = blockIdx.y * 32 + tx;
    const int oy0 = blockIdx.x * 32;
#pragma unroll
    for (int p = 0; p < 4; p++)
        th[(size_t)(oy0 + ty + 8 * p) * DIM + ox] =
            __float2half_rn(t[tx][ty + 8 * p] * sc);
}

// ---------------------------------------------------------------------------
// Row-sum of fp16 E rows (SEQ=2048) -> rinv[row] = 1/sum (fp32).
// ---------------------------------------------------------------------------
__global__ void __launch_bounds__(256)
rowsum_kernel(const __half* __restrict__ E, float* __restrict__ rinv)
{
    const size_t row = blockIdx.x;
    const int tid = threadIdx.x;
    uint4 v = *(const uint4*)(E + row * SEQ + tid * 8);
    const __half2* hp = reinterpret_cast<const __half2*>(&v);
    float s = 0.0f;
#pragma unroll
    for (int j = 0; j < 4; j++) {
        float2 f = __half22float2(hp[j]);
        s += f.x + f.y;
    }
    __shared__ float red[8];
#pragma unroll
    for (int o = 16; o > 0; o >>= 1)
        s += __shfl_xor_sync(0xffffffffu, s, o);
    if ((tid & 31) == 0) red[tid >> 5] = s;
    __syncthreads();
    if (tid == 0) {
        float tot = 0.0f;
#pragma unroll
        for (int w = 0; w < 8; w++) tot += red[w];
        rinv[row] = 1.0f / tot;
    }
}

// ---------------------------------------------------------------------------
// kernel_launch — single QKV + 4-way quarter-split attention:
//   fork0:  sA: transW -> eW   | sB: convert(all) -> eC
//   main:   [eW,eC] QKV (one launch; z==2 epilogue writes Vt) -> evQ
//   s[q]:   [evQ] E = exp2(Q K^T) (2 batches) -> rowsum -> PV*rinv
//           -> outproj(q) -> eJ[q]
//   main:   [eJ0..eJ3] done.
// 4 co-resident GEMM streams fill each other's tensor-pipe bubbles.
// Streams/events created AND destroyed per call; all streams joined back
// into the origin stream before destruction (capture-legal, memory baseline).
// ---------------------------------------------------------------------------
extern "C" void kernel_launch(void* const* d_in, const int* in_sizes, int n_in,
                              void* d_out, int out_size)
{
    (void)in_sizes; (void)n_in; (void)out_size;
    const float* x  = (const float*)d_in[0];
    const float* Wq = (const float*)d_in[1];
    const float* Wk = (const float*)d_in[2];
    const float* Wv = (const float*)d_in[3];
    const float* Wp = (const float*)d_in[4];
    const float* bp = (const float*)d_in[5];
    float* out = (float*)d_out;

    __half *xH, *WtH, *Q, *K, *Vt, *O, *E;
    float* Rinv;
    cudaGetSymbolAddress((void**)&xH, g_xH);
    cudaGetSymbolAddress((void**)&WtH, g_WtH);
    cudaGetSymbolAddress((void**)&Q, g_Q);
    cudaGetSymbolAddress((void**)&K, g_K);
    cudaGetSymbolAddress((void**)&Vt, g_Vt);
    cudaGetSymbolAddress((void**)&O, g_O);
    cudaGetSymbolAddress((void**)&E, g_E);
    cudaGetSymbolAddress((void**)&Rinv, g_Rinv);

    const size_t wstep = (size_t)DIM * DIM;

    cudaFuncSetAttribute(gemmh_kernel<1, false>, cudaFuncAttributeMaxDynamicSharedMemorySize, SM_TOTAL);
    cudaFuncSetAttribute(gemmh_kernel<2, true>,  cudaFuncAttributeMaxDynamicSharedMemorySize, SM_TOTAL);
    cudaFuncSetAttribute(gemmh_kernel<3, false>, cudaFuncAttributeMaxDynamicSharedMemorySize, SM_TOTAL);
    cudaFuncSetAttribute(gemmh_kernel<4, false>, cudaFuncAttributeMaxDynamicSharedMemorySize, SM_TOTAL);

    // Fork plumbing — created per call, destroyed at the end of this call.
    const int NS = 4;
    cudaStream_t s[NS];
    cudaEvent_t evF, eW, eC, evQ, eJ[NS];
    for (int i = 0; i < NS; i++)
        cudaStreamCreateWithFlags(&s[i], cudaStreamNonBlocking);
    cudaEventCreateWithFlags(&evF, cudaEventDisableTiming);
    cudaEventCreateWithFlags(&eW,  cudaEventDisableTiming);
    cudaEventCreateWithFlags(&eC,  cudaEventDisableTiming);
    cudaEventCreateWithFlags(&evQ, cudaEventDisableTiming);
    for (int i = 0; i < NS; i++)
        cudaEventCreateWithFlags(&eJ[i], cudaEventDisableTiming);

    const size_t QB = 2;                       // batches per quarter
    const size_t QROWS = QB * SEQ;             // rows per quarter (4096)
    const size_t qOff = QROWS * DIM;           // fp16 elements per quarter
    const size_t eOff = QB * SEQ * SEQ;        // E elements per quarter

    // ---- fork 0: prep ----
    cudaEventRecord(evF, 0);
    cudaStreamWaitEvent(s[0], evF, 0);
    cudaStreamWaitEvent(s[1], evF, 0);
    {
        dim3 g(DIM / 32, DIM / 32, 4), b(32, 8);
        transW_all_kernel<<<g, b, 0, s[0]>>>(Wq, Wk, Wv, Wp, WtH,
                                             0.03125f * 1.4426950408889634f);
    }
    cudaEventRecord(eW, s[0]);
    convert_fp16_kernel<<<(size_t)MTOT * DIM / 1024, 256, 0, s[1]>>>(x, xH);
    cudaEventRecord(eC, s[1]);

    // ---- main: single QKV launch (z==2 writes Vt transposed in-epilogue) ----
    cudaStreamWaitEvent(0, eW, 0);
    cudaStreamWaitEvent(0, eC, 0);
    {
        dim3 g(DIM / 128, MTOT / 128, 3);
        gemmh_kernel<2, true><<<g, 256, SM_TOTAL>>>(
            xH, WtH, nullptr, Q, K, Vt, nullptr,
            DIM, DIM, 0, wstep, 0, 0);
    }
    cudaEventRecord(evQ, 0);

    // ---- attention quarter-chains (independent, 4 streams) ----
    for (int q = 0; q < NS; q++) {
        cudaStream_t st = s[q];
        cudaStreamWaitEvent(st, evQ, 0);
        const size_t qo = q * qOff;
        const size_t eo = q * eOff;
        float* rinvQ = Rinv + q * QROWS;

        {   // E = exp2(Q K^T) (2 batches, fp16 unnormalized weights)
            dim3 g(SEQ / 128, SEQ / 128, QB);
            gemmh_kernel<3, false><<<g, 256, SM_TOTAL, st>>>(
                Q + qo, K + qo, nullptr, E + eo, nullptr, nullptr, nullptr,
                DIM, SEQ,
                (size_t)SEQ * DIM, (size_t)SEQ * DIM, (size_t)SEQ * SEQ, 0);
        }
        rowsum_kernel<<<QROWS, 256, 0, st>>>(E + eo, rinvQ);
        {   // O = (E @ V) * rinv[row]  (B = Vt, per-batch [DIM, SEQ])
            dim3 g(DIM / 128, SEQ / 128, QB);
            gemmh_kernel<4, false><<<g, 256, SM_TOTAL, st>>>(
                E + eo, Vt + qo, nullptr, O + qo, nullptr, nullptr, rinvQ,
                SEQ, DIM,
                (size_t)SEQ * SEQ, (size_t)DIM * SEQ, (size_t)SEQ * DIM, 0);
        }
        {   // out = O @ Wp^T + bp (this quarter's rows)
            dim3 g(DIM / 128, QROWS / 128, 1);
            gemmh_kernel<1, false><<<g, 256, SM_TOTAL, st>>>(
                O + qo, WtH + 3 * wstep, out + qo, nullptr, nullptr, nullptr, bp,
                DIM, DIM, 0, 0, 0, 0);
        }
        cudaEventRecord(eJ[q], st);
    }

    // ---- join back into origin stream ----
    for (int q = 0; q < NS; q++)
        cudaStreamWaitEvent(0, eJ[q], 0);

    // ---- teardown (streams joined -> out of capture; memory to baseline) ----
    cudaEventDestroy(evF);
    cudaEventDestroy(eW);
    cudaEventDestroy(eC);
    cudaEventDestroy(evQ);
    for (int q = 0; q < NS; q++) cudaEventDestroy(eJ[q]);
    for (int q = 0; q < NS; q++) cudaStreamDestroy(s[q]);
}

// round 17
// speedup vs baseline: 1.0000x; 1.0000x over previous
#include <cuda_runtime.h>
#include <cuda_fp16.h>
#include <stdint.h>
#include <math.h>

#define BATCH 8
#define SEQ   2048
#define DIM   1024
#define MTOT  (BATCH * SEQ)

// ---------------------------------------------------------------------------
// Static device scratch (allocation-free contract). V is never materialized
// (QKV z==2 epilogue writes Vt). S is never materialized in fp32: the E GEMM
// epilogue applies exp2 and writes unnormalized E (fp16); normalization is
// folded into the PV epilogue via per-row 1/sum.
// ---------------------------------------------------------------------------
__device__ __align__(256) __half g_xH[(size_t)MTOT * DIM];
__device__ __align__(256) __half g_WtH[4][(size_t)DIM * DIM];
__device__ __align__(256) __half g_Q[(size_t)MTOT * DIM];
__device__ __align__(256) __half g_K[(size_t)MTOT * DIM];
__device__ __align__(256) __half g_Vt[(size_t)MTOT * DIM];
__device__ __align__(256) __half g_O[(size_t)MTOT * DIM];
__device__ __align__(256) __half g_E[(size_t)BATCH * SEQ * SEQ];
__device__ __align__(256) float  g_Rinv[(size_t)MTOT];

// ---------------------------------------------------------------------------
// Helpers (arch-agnostic PTX only: cp.async / ldmatrix / mma.sync)
// ---------------------------------------------------------------------------
__device__ __forceinline__ uint32_t smem_to_u32(const void* smem_ptr) {
    uint32_t addr;
    asm("{ .reg .u64 tmp; cvta.to.shared.u64 tmp, %1; cvt.u32.u64 %0, tmp; }"
        : "=r"(addr) : "l"(smem_ptr));
    return addr;
}
#define SMEM_SWIZZLE_128B(byte_offset) \
    ((byte_offset) ^ (((byte_offset) >> 3) & 0x70))
#define CP_ASYNC_16(dst_u32, src_ptr) \
    asm volatile("cp.async.cg.shared.global [%0], [%1], 16;" \
                 :: "r"(dst_u32), "l"(src_ptr) : "memory")
#define CP_COMMIT() asm volatile("cp.async.commit_group;" ::: "memory")
#define CP_WAIT(n)  asm volatile("cp.async.wait_group %0;" :: "n"(n) : "memory")

#define LDMATRIX_X4(r0, r1, r2, r3, addr) \
    asm volatile("ldmatrix.sync.aligned.m8n8.x4.shared.b16 {%0,%1,%2,%3}, [%4];" \
                 : "=r"(r0), "=r"(r1), "=r"(r2), "=r"(r3) : "r"(addr))

#define MMA_F16(c, a, b0, b1) \
    asm volatile("mma.sync.aligned.m16n8k16.row.col.f32.f16.f16.f32 " \
                 "{%0,%1,%2,%3}, {%4,%5,%6,%7}, {%8,%9}, {%0,%1,%2,%3};" \
                 : "+f"((c)[0]), "+f"((c)[1]), "+f"((c)[2]), "+f"((c)[3]) \
                 : "r"((a)[0]), "r"((a)[1]), "r"((a)[2]), "r"((a)[3]), \
                   "r"(b0), "r"(b1))

// ---------------------------------------------------------------------------
// GEMM: D[M,N] = A@B^T, single-pass fp16 inputs, fp32 accumulate.
// R8-proven config: tile 128x128, BK=64 (128B rows, SW128), 2-stage cp.async
// double buffer, 8 warps (4m x 2n), warp tile 32x64 m16n8k16, 2 CTAs/SM.
// EPI: 0 = fp32 out, 1 = fp32 + bias, 2 = fp16 out,
//      3 = fp16 exp2(acc) out (unnormalized attention weights E),
//      4 = fp16 acc * rinv[row] out (normalized PV; bias ptr = rinv floats,
//          indexed blockIdx.z * SEQ + row).
// MULTI_B: blockIdx.z selects weight set; z==0 -> Ch (Q), z==1 -> C1 (K),
//          z==2 -> TRANSPOSED fp16 write into C2 as per-batch Vt[DIM,SEQ].
// rowOff: global row offset of this launch's tile grid.
// ---------------------------------------------------------------------------
#define TILE_BYTES 16384            // 128 rows x 128B
#define STAGE_BYTES (2 * TILE_BYTES)
#define SM_TOTAL (2 * STAGE_BYTES)  // 65536

template <int EPI, bool MULTI_B>
__global__ void __launch_bounds__(256, 2)
gemmh_kernel(const __half* __restrict__ A, const __half* __restrict__ B,
             float* __restrict__ Cf, __half* __restrict__ Ch,
             __half* __restrict__ C1, __half* __restrict__ C2,
             const float* __restrict__ bias,
             int K, int ldC, size_t sA, size_t sB, size_t sC, int rowOff)
{
    extern __shared__ char smem[];
    const uint32_t smem_u = smem_to_u32(smem);
    const int tid = threadIdx.x;
    const int lane = tid & 31;
    const int wid = tid >> 5;
    const int warp_m = wid & 3;
    const int warp_n = wid >> 2;
    const int rowBase = rowOff + blockIdx.y * 128;
    const int colBase = blockIdx.x * 128;
    const size_t zA = MULTI_B ? 0 : (size_t)blockIdx.z * sA;
    const size_t zB = (size_t)blockIdx.z * sB;
    const size_t zC = MULTI_B ? 0 : (size_t)blockIdx.z * sC;
    __half* ChSel = Ch;
    if (MULTI_B) ChSel = (blockIdx.z == 0) ? Ch : ((blockIdx.z == 1) ? C1 : C2);

    const int ldr_row0 = tid >> 3;
    const int ldr_ch   = tid & 7;

    float acc[2][8][4];
#pragma unroll
    for (int i = 0; i < 2; i++)
#pragma unroll
        for (int j = 0; j < 8; j++)
#pragma unroll
            for (int e = 0; e < 4; e++) acc[i][j][e] = 0.0f;

    const int nIter = K >> 6;

    auto issue_load = [&](int i, int stage) {
        const int kk = i << 6;
        const __half* As = A + zA;
        const __half* Bs = B + zB;
        const uint32_t aBase = smem_u + stage * STAGE_BYTES;
        const uint32_t bBase = aBase + TILE_BYTES;
#pragma unroll
        for (int p = 0; p < 4; p++) {
            const int row = ldr_row0 + p * 32;
            const uint32_t soff = SMEM_SWIZZLE_128B((uint32_t)row * 128 + ldr_ch * 16);
            CP_ASYNC_16(aBase + soff,
                        As + (size_t)(rowBase + row) * K + kk + ldr_ch * 8);
            CP_ASYNC_16(bBase + soff,
                        Bs + (size_t)(colBase + row) * K + kk + ldr_ch * 8);
        }
        CP_COMMIT();
    };

    issue_load(0, 0);

    for (int i = 0; i < nIter; i++) {
        const int stage = i & 1;
        if (i + 1 < nIter) {
            issue_load(i + 1, (i + 1) & 1);
            CP_WAIT(1);
        } else {
            CP_WAIT(0);
        }
        __syncthreads();

        const uint32_t aBase = smem_u + stage * STAGE_BYTES;
        const uint32_t bBase = aBase + TILE_BYTES;
#pragma unroll
        for (int ks = 0; ks < 4; ks++) {
            const uint32_t k2 = ks * 32;
            uint32_t a[2][4];
            uint32_t b[4][4];
#pragma unroll
            for (int fm = 0; fm < 2; fm++) {
                const uint32_t row = warp_m * 32 + fm * 16 + (lane & 15);
                const uint32_t addr = aBase +
                    SMEM_SWIZZLE_128B(row * 128 + k2 + ((lane >> 4) << 4));
                LDMATRIX_X4(a[fm][0], a[fm][1], a[fm][2], a[fm][3], addr);
            }
#pragma unroll
            for (int fn2 = 0; fn2 < 4; fn2++) {
                const uint32_t n = warp_n * 64 + fn2 * 16 + (lane & 7) + ((lane >> 4) << 3);
                const uint32_t addr = bBase +
                    SMEM_SWIZZLE_128B(n * 128 + k2 + (((lane >> 3) & 1) << 4));
                LDMATRIX_X4(b[fn2][0], b[fn2][1], b[fn2][2], b[fn2][3], addr);
            }
#pragma unroll
            for (int fn2 = 0; fn2 < 4; fn2++) {
                MMA_F16(acc[0][fn2 * 2 + 0], a[0], b[fn2][0], b[fn2][1]);
                MMA_F16(acc[0][fn2 * 2 + 1], a[0], b[fn2][2], b[fn2][3]);
                MMA_F16(acc[1][fn2 * 2 + 0], a[1], b[fn2][0], b[fn2][1]);
                MMA_F16(acc[1][fn2 * 2 + 1], a[1], b[fn2][2], b[fn2][3]);
            }
        }
        __syncthreads();
    }

    // Epilogue
    const int gid = lane >> 2;
    const int tig = lane & 3;

    if (EPI == 2 && MULTI_B && blockIdx.z == 2) {
        // ---- transposed V output: stage tile in smem, write Vt[d, t] ----
        __half* tsm = reinterpret_cast<__half*>(smem);   // [128][130] fp16
#pragma unroll
        for (int fm = 0; fm < 2; fm++) {
#pragma unroll
            for (int fn = 0; fn < 8; fn++) {
                const int r = warp_m * 32 + fm * 16 + gid;     // tile-local t
                const int c = warp_n * 64 + fn * 8 + tig * 2;  // tile-local d
                const float* ac = acc[fm][fn];
                __half2 h0 = __floats2half2_rn(ac[0], ac[1]);
                __half2 h1 = __floats2half2_rn(ac[2], ac[3]);
                *(__half2*)(&tsm[(size_t)r * 130 + c])       = h0;
                *(__half2*)(&tsm[(size_t)(r + 8) * 130 + c]) = h1;
            }
        }
        __syncthreads();
        const int gRow0 = rowBase;                    // 128-aligned, within one batch
        const size_t bidx = (size_t)gRow0 / SEQ;
        const int tl0 = gRow0 % SEQ;
        __half* dstBase = C2 + bidx * (size_t)DIM * SEQ + tl0;
#pragma unroll 1
        for (int ccb = 0; ccb < 16; ccb++) {
            const int cc = wid * 16 + ccb;            // tile-local d
            __half* drow = dstBase + (size_t)(colBase + cc) * SEQ;
#pragma unroll
            for (int j = 0; j < 4; j++) {
                const int t = lane + 32 * j;
                drow[t] = tsm[(size_t)t * 130 + cc];
            }
        }
        return;
    }

#pragma unroll
    for (int fm = 0; fm < 2; fm++) {
#pragma unroll
        for (int fn = 0; fn < 8; fn++) {
            const int r0 = rowBase + warp_m * 32 + fm * 16 + gid;
            const int c  = colBase + warp_n * 64 + fn * 8 + tig * 2;
            const float* ac = acc[fm][fn];
            if (EPI == 2) {
                __half2 h0 = __floats2half2_rn(ac[0], ac[1]);
                __half2 h1 = __floats2half2_rn(ac[2], ac[3]);
                *(uint32_t*)(ChSel + zC + (size_t)r0 * ldC + c)       = *(uint32_t*)&h0;
                *(uint32_t*)(ChSel + zC + (size_t)(r0 + 8) * ldC + c) = *(uint32_t*)&h1;
            } else if (EPI == 3) {
                __half2 h0 = __floats2half2_rn(exp2f(ac[0]), exp2f(ac[1]));
                __half2 h1 = __floats2half2_rn(exp2f(ac[2]), exp2f(ac[3]));
                *(uint32_t*)(ChSel + zC + (size_t)r0 * ldC + c)       = *(uint32_t*)&h0;
                *(uint32_t*)(ChSel + zC + (size_t)(r0 + 8) * ldC + c) = *(uint32_t*)&h1;
            } else if (EPI == 4) {
                const float rs0 = bias[(size_t)blockIdx.z * SEQ + r0];
                const float rs1 = bias[(size_t)blockIdx.z * SEQ + r0 + 8];
                __half2 h0 = __floats2half2_rn(ac[0] * rs0, ac[1] * rs0);
                __half2 h1 = __floats2half2_rn(ac[2] * rs1, ac[3] * rs1);
                *(uint32_t*)(ChSel + zC + (size_t)r0 * ldC + c)       = *(uint32_t*)&h0;
                *(uint32_t*)(ChSel + zC + (size_t)(r0 + 8) * ldC + c) = *(uint32_t*)&h1;
            } else {
                float2 v0 = make_float2(ac[0], ac[1]);
                float2 v1 = make_float2(ac[2], ac[3]);
                if (EPI == 1) {
                    const float b0 = bias[c], b1 = bias[c + 1];
                    v0.x += b0; v0.y += b1;
                    v1.x += b0; v1.y += b1;
                }
                *(float2*)(Cf + zC + (size_t)r0 * ldC + c)       = v0;
                *(float2*)(Cf + zC + (size_t)(r0 + 8) * ldC + c) = v1;
            }
        }
    }
}

// ---------------------------------------------------------------------------
// fp32 -> fp16 convert (elementwise)
// ---------------------------------------------------------------------------
__global__ void __launch_bounds__(256)
convert_fp16_kernel(const float* __restrict__ x, __half* __restrict__ h)
{
    size_t i = ((size_t)blockIdx.x * 256 + threadIdx.x) * 4;
    float4 v = *(const float4*)(x + i);
    __half2 a = __floats2half2_rn(v.x, v.y);
    __half2 b = __floats2half2_rn(v.z, v.w);
    *(uint2*)(h + i) = make_uint2(*(uint32_t*)&a, *(uint32_t*)&b);
}

// ---------------------------------------------------------------------------
// Transpose + convert ALL FOUR weight matrices in one launch.
// Wq (z==0) pre-scaled by scale*log2e -> E = exp2(logit) directly.
// ---------------------------------------------------------------------------
__global__ void __launch_bounds__(256)
transW_all_kernel(const float* __restrict__ W0, const float* __restrict__ W1,
                  const float* __restrict__ W2, const float* __restrict__ W3,
                  __half* __restrict__ thB, float qscale)
{
    const float* W = (blockIdx.z == 0) ? W0 :
                     (blockIdx.z == 1) ? W1 :
                     (blockIdx.z == 2) ? W2 : W3;
    const float sc = (blockIdx.z == 0) ? qscale : 1.0f;
    __half* th = thB + (size_t)blockIdx.z * DIM * DIM;
    __shared__ float t[32][33];
    const int tx = threadIdx.x, ty = threadIdx.y;
    const int x = blockIdx.x * 32 + tx;
    const int y0 = blockIdx.y * 32;
#pragma unroll
    for (int p = 0; p < 4; p++)
        t[ty + 8 * p][tx] = W[(size_t)(y0 + ty + 8 * p) * DIM + x];
    __syncthreads();
    const int ox = blockIdx.y * 32 + tx;
    const int oy0 = blockIdx.x * 32;
#pragma unroll
    for (int p = 0; p < 4; p++)
        th[(size_t)(oy0 + ty + 8 * p) * DIM + ox] =
            __float2half_rn(t[tx][ty + 8 * p] * sc);
}

// ---------------------------------------------------------------------------
// Row-sum of fp16 E rows (SEQ=2048) -> rinv[row] = 1/sum (fp32).
// ---------------------------------------------------------------------------
__global__ void __launch_bounds__(256)
rowsum_kernel(const __half* __restrict__ E, float* __restrict__ rinv)
{
    const size_t row = blockIdx.x;
    const int tid = threadIdx.x;
    uint4 v = *(const uint4*)(E + row * SEQ + tid * 8);
    const __half2* hp = reinterpret_cast<const __half2*>(&v);
    float s = 0.0f;
#pragma unroll
    for (int j = 0; j < 4; j++) {
        float2 f = __half22float2(hp[j]);
        s += f.x + f.y;
    }
    __shared__ float red[8];
#pragma unroll
    for (int o = 16; o > 0; o >>= 1)
        s += __shfl_xor_sync(0xffffffffu, s, o);
    if ((tid & 31) == 0) red[tid >> 5] = s;
    __syncthreads();
    if (tid == 0) {
        float tot = 0.0f;
#pragma unroll
        for (int w = 0; w < 8; w++) tot += red[w];
        rinv[row] = 1.0f / tot;
    }
}

// ---------------------------------------------------------------------------
// kernel_launch — single QKV + 2-way half-split attention (best measured
// components of R15/R16 recombined):
//   fork0:  s1: transW -> eW   | s2: convert(all) -> eC
//   main:   [eW,eC] QKV (one launch; z==2 epilogue writes Vt) -> evQ
//   s[h]:   [evQ] E = exp2(Q K^T) (4 batches) -> rowsum -> PV*rinv
//           -> outproj(h) -> eJ[h]
//   main:   [eJ0,eJ1] done.
// Streams/events created AND destroyed per call; all streams joined back
// into the origin stream before destruction (capture-legal, memory baseline).
// ---------------------------------------------------------------------------
extern "C" void kernel_launch(void* const* d_in, const int* in_sizes, int n_in,
                              void* d_out, int out_size)
{
    (void)in_sizes; (void)n_in; (void)out_size;
    const float* x  = (const float*)d_in[0];
    const float* Wq = (const float*)d_in[1];
    const float* Wk = (const float*)d_in[2];
    const float* Wv = (const float*)d_in[3];
    const float* Wp = (const float*)d_in[4];
    const float* bp = (const float*)d_in[5];
    float* out = (float*)d_out;

    __half *xH, *WtH, *Q, *K, *Vt, *O, *E;
    float* Rinv;
    cudaGetSymbolAddress((void**)&xH, g_xH);
    cudaGetSymbolAddress((void**)&WtH, g_WtH);
    cudaGetSymbolAddress((void**)&Q, g_Q);
    cudaGetSymbolAddress((void**)&K, g_K);
    cudaGetSymbolAddress((void**)&Vt, g_Vt);
    cudaGetSymbolAddress((void**)&O, g_O);
    cudaGetSymbolAddress((void**)&E, g_E);
    cudaGetSymbolAddress((void**)&Rinv, g_Rinv);

    const size_t wstep = (size_t)DIM * DIM;

    cudaFuncSetAttribute(gemmh_kernel<1, false>, cudaFuncAttributeMaxDynamicSharedMemorySize, SM_TOTAL);
    cudaFuncSetAttribute(gemmh_kernel<2, true>,  cudaFuncAttributeMaxDynamicSharedMemorySize, SM_TOTAL);
    cudaFuncSetAttribute(gemmh_kernel<3, false>, cudaFuncAttributeMaxDynamicSharedMemorySize, SM_TOTAL);
    cudaFuncSetAttribute(gemmh_kernel<4, false>, cudaFuncAttributeMaxDynamicSharedMemorySize, SM_TOTAL);

    // Fork plumbing — created per call, destroyed at the end of this call.
    cudaStream_t s1, s2;
    cudaEvent_t evF, eW, eC, evQ, eJ1, eJ2;
    cudaStreamCreateWithFlags(&s1, cudaStreamNonBlocking);
    cudaStreamCreateWithFlags(&s2, cudaStreamNonBlocking);
    cudaEventCreateWithFlags(&evF, cudaEventDisableTiming);
    cudaEventCreateWithFlags(&eW,  cudaEventDisableTiming);
    cudaEventCreateWithFlags(&eC,  cudaEventDisableTiming);
    cudaEventCreateWithFlags(&evQ, cudaEventDisableTiming);
    cudaEventCreateWithFlags(&eJ1, cudaEventDisableTiming);
    cudaEventCreateWithFlags(&eJ2, cudaEventDisableTiming);

    const size_t HB = 4;                       // batches per half
    const size_t HROWS = HB * SEQ;             // rows per half (8192)
    const size_t qkvOff = HROWS * DIM;         // fp16 elements per half
    const size_t sOff   = HB * SEQ * SEQ;      // E elements per half

    // ---- fork 0: prep ----
    cudaEventRecord(evF, 0);
    cudaStreamWaitEvent(s1, evF, 0);
    cudaStreamWaitEvent(s2, evF, 0);
    {
        dim3 g(DIM / 32, DIM / 32, 4), b(32, 8);
        transW_all_kernel<<<g, b, 0, s1>>>(Wq, Wk, Wv, Wp, WtH,
                                           0.03125f * 1.4426950408889634f);
    }
    cudaEventRecord(eW, s1);
    convert_fp16_kernel<<<(size_t)MTOT * DIM / 1024, 256, 0, s2>>>(x, xH);
    cudaEventRecord(eC, s2);

    // ---- main: single QKV launch (z==2 writes Vt transposed in-epilogue) ----
    cudaStreamWaitEvent(0, eW, 0);
    cudaStreamWaitEvent(0, eC, 0);
    {
        dim3 g(DIM / 128, MTOT / 128, 3);
        gemmh_kernel<2, true><<<g, 256, SM_TOTAL>>>(
            xH, WtH, nullptr, Q, K, Vt, nullptr,
            DIM, DIM, 0, wstep, 0, 0);
    }
    cudaEventRecord(evQ, 0);

    // ---- attention half-chains (independent, 2 streams) ----
    for (int h = 0; h < 2; h++) {
        cudaStream_t st = h ? s2 : s1;
        cudaStreamWaitEvent(st, evQ, 0);
        const size_t qo = h * qkvOff;
        const size_t so = h * sOff;
        float* rinvH = Rinv + h * HROWS;

        {   // E = exp2(Q K^T) (4 batches, fp16 unnormalized weights)
            dim3 g(SEQ / 128, SEQ / 128, HB);
            gemmh_kernel<3, false><<<g, 256, SM_TOTAL, st>>>(
                Q + qo, K + qo, nullptr, E + so, nullptr, nullptr, nullptr,
                DIM, SEQ,
                (size_t)SEQ * DIM, (size_t)SEQ * DIM, (size_t)SEQ * SEQ, 0);
        }
        rowsum_kernel<<<HROWS, 256, 0, st>>>(E + so, rinvH);
        {   // O = (E @ V) * rinv[row]  (B = Vt, per-batch [DIM, SEQ])
            dim3 g(DIM / 128, SEQ / 128, HB);
            gemmh_kernel<4, false><<<g, 256, SM_TOTAL, st>>>(
                E + so, Vt + qo, nullptr, O + qo, nullptr, nullptr, rinvH,
                SEQ, DIM,
                (size_t)SEQ * SEQ, (size_t)DIM * SEQ, (size_t)SEQ * DIM, 0);
        }
        {   // out = O @ Wp^T + bp (this half's rows)
            dim3 g(DIM / 128, HROWS / 128, 1);
            gemmh_kernel<1, false><<<g, 256, SM_TOTAL, st>>>(
                O + qo, WtH + 3 * wstep, out + qo, nullptr, nullptr, nullptr, bp,
                DIM, DIM, 0, 0, 0, 0);
        }
        cudaEventRecord(h ? eJ2 : eJ1, st);
    }

    // ---- join back into origin stream ----
    cudaStreamWaitEvent(0, eJ1, 0);
    cudaStreamWaitEvent(0, eJ2, 0);

    // ---- teardown (streams joined -> out of capture; memory to baseline) ----
    cudaEventDestroy(evF);
    cudaEventDestroy(eW);
    cudaEventDestroy(eC);
    cudaEventDestroy(evQ);
    cudaEventDestroy(eJ1);
    cudaEventDestroy(eJ2);
    cudaStreamDestroy(s1);
    cudaStreamDestroy(s2);
}